// round 14
// baseline (speedup 1.0000x reference)
#include <cuda_runtime.h>
#include <cuda_fp16.h>
#include <cstdint>

#define T_TOK   32768
#define IN_DIM  2048
#define OUT_DIM 768
#define NEXP    64
#define RRANK   16
#define SCALING 2.0f

#define BM 128
#define BN 96
#define BK 32
#define KT3 (IN_DIM / BK)                  /* 64 stages */
#define MAX_MTILES 320
#define NT 8                               /* 768 / 96 */
#define NTHREADS 128                       /* 4 warps, 2m x 2n, warp tile 64x48 */

#define CVT_BLOCKS 4096
#define PRE_GRID (MAX_MTILES + CVT_BLOCKS)

// smem row strides (bytes), conflict-free for ldmatrix (stride/16 odd)
#define SA  80    /* A: 32 halves + pad;  5r mod 8 distinct  */
#define SB  208   /* B: 96 halves + pad;  13k mod 8 distinct */
#define SAC 48    /* a-tile: 16 halves + pad */

#define A_STG  (128 * SA)   /* 10240 */
#define B_STG  (32 * SB)    /* 6656  */

#define SM_A   0                           /* 4 stages: 40960 */
#define SM_B   (4 * A_STG)                 /* 40960, 4 stages: 26624 */
#define SM_MSZ (SM_B + 4 * B_STG)          /* 67584 */
#define SMEM_BYTES (SM_MSZ + 256)          /* 67840; 3 CTAs/SM (203.5KB) */

// fp16 scratch
__device__ __align__(16) __half g_xh [(size_t)T_TOK * IN_DIM];
__device__ __align__(16) __half g_wbh[(size_t)NEXP * IN_DIM * OUT_DIM];
__device__ __align__(16) __half g_wsh[(size_t)NEXP * RRANK * OUT_DIM];
__device__ __align__(16) __half g_ah [(size_t)T_TOK * RRANK];   /* a * SCALING */

__device__ __forceinline__ uint32_t h2u(__half2 h) {
    return *reinterpret_cast<uint32_t*>(&h);
}

__device__ __forceinline__ void cp16(uint32_t dst, const void* src, bool valid) {
    int sz = valid ? 16 : 0;   // sz=0 zero-fills, reads nothing
    asm volatile("cp.async.cg.shared.global [%0], [%1], 16, %2;\n"
                 :: "r"(dst), "l"(src), "r"(sz));
}

__device__ __forceinline__ void ldsm_x4(uint32_t* r, uint32_t addr) {
    asm volatile("ldmatrix.sync.aligned.m8n8.x4.shared.b16 {%0,%1,%2,%3}, [%4];"
                 : "=r"(r[0]), "=r"(r[1]), "=r"(r[2]), "=r"(r[3]) : "r"(addr));
}
__device__ __forceinline__ void ldsm_x4_t(uint32_t* r, uint32_t addr) {
    asm volatile("ldmatrix.sync.aligned.m8n8.x4.trans.shared.b16 {%0,%1,%2,%3}, [%4];"
                 : "=r"(r[0]), "=r"(r[1]), "=r"(r[2]), "=r"(r[3]) : "r"(addr));
}

__device__ __forceinline__ void mma_f16(float* c, const uint32_t* a,
                                        uint32_t b0, uint32_t b1) {
    asm volatile(
        "mma.sync.aligned.m16n8k16.row.col.f32.f16.f16.f32 "
        "{%0,%1,%2,%3},{%4,%5,%6,%7},{%8,%9},{%0,%1,%2,%3};"
        : "+f"(c[0]), "+f"(c[1]), "+f"(c[2]), "+f"(c[3])
        : "r"(a[0]), "r"(a[1]), "r"(a[2]), "r"(a[3]), "r"(b0), "r"(b1));
}

// ---- tile scan helper ----
__device__ __forceinline__ int tile_scan(const int* msz, int mt, int* e_out,
                                         int* row_out, int* mlen_out) {
    int acc_rows = 0, acc_tiles = 0;
    for (int e = 0; e < NEXP; e++) {
        int m  = msz[e];
        int nt = (m + BM - 1) >> 7;
        if (mt < acc_tiles + nt) {
            int lt    = mt - acc_tiles;
            *e_out    = e;
            *row_out  = acc_rows + lt * BM;
            *mlen_out = min(BM, m - lt * BM);
            return 1;
        }
        acc_tiles += nt;
        acc_rows  += m;
    }
    return 0;
}

// ---- merged prepass: blocks [0,320) = x-cvt + lora-A; blocks >=320 = w cvt ----
#define LSA 80   /* x smem stride (bytes) */
#define LSW 48   /* w_a smem stride */
__global__ void __launch_bounds__(128)
prepass_kernel(const float* __restrict__ x,
               const int*   __restrict__ m_sizes,
               const float* __restrict__ w_a,
               const float4* __restrict__ wb_src,   /* w_base fp32 */
               const float4* __restrict__ ws_src)   /* w_b fp32 */
{
    __shared__ __align__(128) char smem[2 * 128 * LSA + 2 * 32 * LSW + 256];
    const int tid = threadIdx.x;

    if (blockIdx.x >= MAX_MTILES) {
        // ---- streaming fp32->fp16 convert of w_base then w_b ----
        const int nwb = (int)((size_t)NEXP * IN_DIM * OUT_DIM / 4);
        const int nws = (int)((size_t)NEXP * RRANK * OUT_DIM / 4);
        const int ntot = nwb + nws;
        uint2* wb_dst = (uint2*)g_wbh;
        uint2* ws_dst = (uint2*)g_wsh;
        const int stride = CVT_BLOCKS * 128;
        for (int i = (blockIdx.x - MAX_MTILES) * 128 + tid; i < ntot; i += stride) {
            float4 f;
            if (i < nwb) f = wb_src[i];
            else         f = ws_src[i - nwb];
            uint2 u;
            u.x = h2u(__floats2half2_rn(f.x, f.y));
            u.y = h2u(__floats2half2_rn(f.z, f.w));
            if (i < nwb) wb_dst[i] = u;
            else         ws_dst[i - nwb] = u;
        }
        return;
    }

    // ---- lora-A path (block = one m-tile) ----
    char* Xs  = smem;
    char* Was = smem + 2 * 128 * LSA;
    int*  msz = (int*)(smem + 2 * 128 * LSA + 2 * 32 * LSW);
    const uint32_t sbx = (uint32_t)__cvta_generic_to_shared(Xs);
    const uint32_t sbw = (uint32_t)__cvta_generic_to_shared(Was);

    const int lane = tid & 31;
    const int warp = tid >> 5;

    if (tid < NEXP) msz[tid] = m_sizes[tid];
    __syncthreads();

    int e, row_start, m_len;
    if (!tile_scan(msz, blockIdx.x, &e, &row_start, &m_len)) return;

    const float* xg = x   + (size_t)row_start * IN_DIM;
    const float* ag = w_a + (size_t)e * IN_DIM * RRANK;
    __half*      xo = g_xh + (size_t)row_start * IN_DIM;

    float acc[2][2][4];   // warp tile 32x16
    #pragma unroll
    for (int i = 0; i < 2; i++)
        #pragma unroll
        for (int j = 0; j < 2; j++)
            #pragma unroll
            for (int q = 0; q < 4; q++) acc[i][j][q] = 0.f;

    float4 fx[8], fw;

    auto load_regs = [&](int kt) {
        const int k0 = kt * BK;
        #pragma unroll
        for (int j = 0; j < 8; j++) {
            int idx = tid + j * 128;
            int row = idx >> 3, c = idx & 7;
            bool v = (row_start + row) < T_TOK;
            fx[j] = v ? *(const float4*)(xg + (size_t)row * IN_DIM + k0 + c * 4)
                      : make_float4(0.f, 0.f, 0.f, 0.f);
        }
        {
            int k = tid >> 2, rq = tid & 3;
            fw = *(const float4*)(ag + (size_t)(k0 + k) * RRANK + rq * 4);
        }
    };

    auto store_stage = [&](int kt) {
        const int st = kt & 1;
        char* X = Xs  + st * 128 * LSA;
        char* W = Was + st * 32 * LSW;
        const int k0 = kt * BK;
        #pragma unroll
        for (int j = 0; j < 8; j++) {
            int idx = tid + j * 128;
            int row = idx >> 3, c = idx & 7;
            uint2 u;
            u.x = h2u(__floats2half2_rn(fx[j].x, fx[j].y));
            u.y = h2u(__floats2half2_rn(fx[j].z, fx[j].w));
            *(uint2*)(X + row * LSA + c * 8) = u;
            if ((row_start + row) < T_TOK)
                *(uint2*)(xo + (size_t)row * IN_DIM + k0 + c * 4) = u;
        }
        {
            int k = tid >> 2, rq = tid & 3;
            uint2 u;
            u.x = h2u(__floats2half2_rn(fw.x, fw.y));
            u.y = h2u(__floats2half2_rn(fw.z, fw.w));
            *(uint2*)(W + k * LSW + rq * 8) = u;
        }
    };

    const uint32_t a_off = (uint32_t)((warp * 32 + (lane & 15)) * LSA + (lane >> 4) * 16);
    const uint32_t w_off = (uint32_t)((lane & 15) * LSW + (lane >> 4) * 16);

    auto compute = [&](int kt) {
        const int st = kt & 1;
        const uint32_t Xb = sbx + st * 128 * LSA + a_off;
        const uint32_t Wb = sbw + st * 32 * LSW + w_off;
        #pragma unroll
        for (int ks = 0; ks < 2; ks++) {
            uint32_t am[2][4];
            ldsm_x4(am[0], Xb + ks * 32);
            ldsm_x4(am[1], Xb + ks * 32 + 16 * LSA);
            uint32_t bf[4];
            ldsm_x4_t(bf, Wb + ks * 16 * LSW);
            #pragma unroll
            for (int mf = 0; mf < 2; mf++) {
                mma_f16(acc[mf][0], am[mf], bf[0], bf[1]);
                mma_f16(acc[mf][1], am[mf], bf[2], bf[3]);
            }
        }
    };

    load_regs(0);
    store_stage(0);
    __syncthreads();
    #pragma unroll 1
    for (int kt = 0; kt < KT3; kt++) {
        if (kt + 1 < KT3) load_regs(kt + 1);
        compute(kt);
        if (kt + 1 < KT3) {
            store_stage(kt + 1);
            __syncthreads();
        }
    }

    // store a * SCALING (only rows of THIS expert)
    {
        const int r0 = warp * 32 + (lane >> 2);
        const int c0 = 2 * (lane & 3);
        #pragma unroll
        for (int mf = 0; mf < 2; mf++) {
            #pragma unroll
            for (int nf = 0; nf < 2; nf++) {
                int r = r0 + mf * 16, c = nf * 8 + c0;
                if (r < m_len)
                    *(__half2*)(g_ah + (size_t)(row_start + r) * RRANK + c) =
                        __floats2half2_rn(acc[mf][nf][0] * SCALING,
                                          acc[mf][nf][1] * SCALING);
                if (r + 8 < m_len)
                    *(__half2*)(g_ah + (size_t)(row_start + r + 8) * RRANK + c) =
                        __floats2half2_rn(acc[mf][nf][2] * SCALING,
                                          acc[mf][nf][3] * SCALING);
            }
        }
    }
}

// ---- main GEMM: y = x @ w_base[e] + a2 @ w_b[e], BN=96, 3 CTAs/SM ----
__global__ __launch_bounds__(NTHREADS, 3)
void lora_moe_hA(const int* __restrict__ m_sizes, float* __restrict__ out) {
    extern __shared__ __align__(128) char smem[];
    const uint32_t sb = (uint32_t)__cvta_generic_to_shared(smem);

    const int tid  = threadIdx.x;
    const int lane = tid & 31;
    const int warp = tid >> 5;
    const int wm   = warp & 1;   // m half (64 rows)
    const int wn   = warp >> 1;  // n half (48 cols)

    int* msz = (int*)(smem + SM_MSZ);
    if (tid < NEXP) msz[tid] = m_sizes[tid];
    __syncthreads();

    int e, row_start, m_len;
    if (!tile_scan(msz, blockIdx.y, &e, &row_start, &m_len)) return;

    const int n0 = blockIdx.x * BN;
    const __half* xg  = g_xh  + (size_t)row_start * IN_DIM;
    const __half* bg  = g_wbh + (size_t)e * IN_DIM * OUT_DIM + n0;
    const __half* wbg = g_wsh + (size_t)e * RRANK  * OUT_DIM + n0;

    float acc[4][6][4];    // 4 m-frags x 6 n-frags (96 regs)
    #pragma unroll
    for (int i = 0; i < 4; i++)
        #pragma unroll
        for (int j = 0; j < 6; j++)
            #pragma unroll
            for (int q = 0; q < 4; q++) acc[i][j][q] = 0.f;

    auto load_stage = [&](int kt) {
        const int st = kt & 3;
        const uint32_t A = sb + SM_A + st * A_STG;
        const uint32_t B = sb + SM_B + st * B_STG;
        const int k0 = kt * BK;
        // A: 128 rows x 4 chunks = 512 chunks
        #pragma unroll
        for (int j = 0; j < 4; j++) {
            int idx = tid + j * NTHREADS;
            int row = idx >> 2, kc = idx & 3;
            bool v = (row_start + row) < T_TOK;
            cp16(A + row * SA + kc * 16, xg + (size_t)row * IN_DIM + k0 + kc * 8, v);
        }
        // B: 32 rows x 12 chunks = 384 chunks, 3 per thread
        #pragma unroll
        for (int j = 0; j < 3; j++) {
            int idx = tid + j * NTHREADS;
            int k = idx / 12, nq = idx % 12;
            cp16(B + k * SB + nq * 16, bg + (size_t)(k0 + k) * OUT_DIM + nq * 8, true);
        }
        asm volatile("cp.async.commit_group;\n");
    };

    const uint32_t a_off = (uint32_t)((wm * 64 + (lane & 15)) * SA + (lane >> 4) * 16);
    const uint32_t b_off = (uint32_t)((lane & 15) * SB + wn * 96 + (lane >> 4) * 16);

    auto compute = [&](int kt) {
        const int st = kt & 3;
        const uint32_t Ab = sb + SM_A + st * A_STG + a_off;
        const uint32_t Bb = sb + SM_B + st * B_STG + b_off;
        #pragma unroll
        for (int ks = 0; ks < 2; ks++) {
            uint32_t am[4][4];
            #pragma unroll
            for (int mf = 0; mf < 4; mf++)
                ldsm_x4(am[mf], Ab + mf * 16 * SA + ks * 32);
            #pragma unroll
            for (int p = 0; p < 3; p++) {
                uint32_t bf[4];
                ldsm_x4_t(bf, Bb + ks * 16 * SB + p * 32);
                #pragma unroll
                for (int mf = 0; mf < 4; mf++) {
                    mma_f16(acc[mf][2 * p],     am[mf], bf[0], bf[1]);
                    mma_f16(acc[mf][2 * p + 1], am[mf], bf[2], bf[3]);
                }
            }
        }
    };

    // ---- 4-stage pipeline, depth-3 flight, one barrier per stage ----
    load_stage(0);
    load_stage(1);
    load_stage(2);
    #pragma unroll 1
    for (int kt = 0; kt < KT3; kt++) {
        if (kt < KT3 - 2)       asm volatile("cp.async.wait_group 2;\n");
        else if (kt == KT3 - 2) asm volatile("cp.async.wait_group 1;\n");
        else                    asm volatile("cp.async.wait_group 0;\n");
        __syncthreads();
        if (kt + 3 < KT3) load_stage(kt + 3);
        compute(kt);
    }
    __syncthreads();

    // ---- LoRA epilogue: load a2 (g_ah) + w_b, one K=16 mma pass ----
    {
        const uint32_t Asc = sb + SM_A;
        #pragma unroll
        for (int j = 0; j < 2; j++) {
            int idx = tid + j * NTHREADS;       // 0..255
            int row = idx >> 1, c = idx & 1;
            bool v = (row_start + row) < T_TOK;
            cp16(Asc + row * SAC + c * 16,
                 g_ah + (size_t)(row_start + row) * RRANK + c * 8, v);
        }
        asm volatile("cp.async.commit_group;\n");
        // w_b: 16 rows x 12 chunks = 192 chunks
        char* Wbs = smem + SM_B;
        #pragma unroll
        for (int j = 0; j < 2; j++) {
            int idx = tid + j * NTHREADS;
            if (idx < 192) {
                int k = idx / 12, nq = idx % 12;
                uint4 v = *(const uint4*)(wbg + (size_t)k * OUT_DIM + nq * 8);
                *(uint4*)(Wbs + k * SB + nq * 16) = v;
            }
        }
        asm volatile("cp.async.wait_group 0;\n");
    }
    __syncthreads();

    {
        const int row = wm * 64 + (lane >> 2);
        uint32_t am[4][4];
        #pragma unroll
        for (int mf = 0; mf < 4; mf++) {
            const uint32_t base = sb + SM_A + (row + mf * 16) * SAC + (lane & 3) * 4;
            asm volatile("ld.shared.b32 %0, [%1];" : "=r"(am[mf][0]) : "r"(base));
            asm volatile("ld.shared.b32 %0, [%1];" : "=r"(am[mf][1]) : "r"(base + 8 * SAC));
            asm volatile("ld.shared.b32 %0, [%1];" : "=r"(am[mf][2]) : "r"(base + 16));
            asm volatile("ld.shared.b32 %0, [%1];" : "=r"(am[mf][3]) : "r"(base + 8 * SAC + 16));
        }
        const uint32_t Bb = sb + SM_B + b_off;
        #pragma unroll
        for (int p = 0; p < 3; p++) {
            uint32_t bf[4];
            ldsm_x4_t(bf, Bb + p * 32);
            #pragma unroll
            for (int mf = 0; mf < 4; mf++) {
                mma_f16(acc[mf][2 * p],     am[mf], bf[0], bf[1]);
                mma_f16(acc[mf][2 * p + 1], am[mf], bf[2], bf[3]);
            }
        }
    }

    // ---- store ----
    {
        float* og = out + (size_t)row_start * OUT_DIM + n0;
        const int r0s = wm * 64 + (lane >> 2);
        const int c0s = wn * 48 + 2 * (lane & 3);
        #pragma unroll
        for (int mf = 0; mf < 4; mf++) {
            const int r1 = r0s + mf * 16;
            #pragma unroll
            for (int nf = 0; nf < 6; nf++) {
                const int cc = c0s + nf * 8;
                if (r1 < m_len)
                    *reinterpret_cast<float2*>(og + (size_t)r1 * OUT_DIM + cc) =
                        make_float2(acc[mf][nf][0], acc[mf][nf][1]);
                if (r1 + 8 < m_len)
                    *reinterpret_cast<float2*>(og + (size_t)(r1 + 8) * OUT_DIM + cc) =
                        make_float2(acc[mf][nf][2], acc[mf][nf][3]);
            }
        }
    }
}

extern "C" void kernel_launch(void* const* d_in, const int* in_sizes, int n_in,
                              void* d_out, int out_size) {
    const float* x      = (const float*)d_in[0];
    const int*   msz    = (const int*)  d_in[1];
    const float* w_base = (const float*)d_in[2];
    const float* w_a    = (const float*)d_in[3];
    const float* w_b    = (const float*)d_in[4];
    float*       out    = (float*)d_out;

    prepass_kernel<<<PRE_GRID, 128>>>(x, msz, w_a,
                                      (const float4*)w_base, (const float4*)w_b);

    static int cfg_done = 0;
    if (!cfg_done) {
        cudaFuncSetAttribute(lora_moe_hA,
                             cudaFuncAttributeMaxDynamicSharedMemorySize, SMEM_BYTES);
        cfg_done = 1;
    }
    dim3 grid(NT, MAX_MTILES);
    lora_moe_hA<<<grid, NTHREADS, SMEM_BYTES>>>(msz, out);
}

// round 15
// speedup vs baseline: 1.1794x; 1.1794x over previous
#include <cuda_runtime.h>
#include <cuda_fp16.h>
#include <cstdint>

#define T_TOK   32768
#define IN_DIM  2048
#define OUT_DIM 768
#define NEXP    64
#define RRANK   16
#define SCALING 2.0f

#define BM 128
#define BN 128
#define BK 32
#define KT3 (IN_DIM / BK)                  /* 64 stages */
#define MAX_MTILES 320
#define NT 6
#define NTHREADS 128                       /* main: 4 warps, 2m x 2n, 64x64 */
#define PTHREADS 256                       /* prepass threads */

#define CVT_BLOCKS 4096
#define PRE_GRID (MAX_MTILES + CVT_BLOCKS)

// smem row strides (bytes), conflict-free for ldmatrix (stride/16 odd)
#define SA  80    /* A: 32 halves + pad;  5r mod 8 distinct  */
#define SB  272   /* B: 128 halves + pad; 17k mod 8 distinct */
#define SAC 48    /* a-tile: 16 halves + pad */

#define A_STG  (128 * SA)   /* 10240 */
#define B_STG  (32 * SB)    /* 8704  */

#define SM_A   0                           /* 4 stages: 40960 */
#define SM_B   (4 * A_STG)                 /* 40960, 4 stages: 34816 */
#define SM_MSZ (SM_B + 4 * B_STG)          /* 75776 */
#define SMEM_BYTES (SM_MSZ + 256)          /* 76032; 2 CTAs/SM */

// fp16 scratch
__device__ __align__(16) __half g_xh [(size_t)T_TOK * IN_DIM];
__device__ __align__(16) __half g_wbh[(size_t)NEXP * IN_DIM * OUT_DIM];
__device__ __align__(16) __half g_wsh[(size_t)NEXP * RRANK * OUT_DIM];
__device__ __align__(16) __half g_ah [(size_t)T_TOK * RRANK];   /* a * SCALING */

__device__ __forceinline__ uint32_t h2u(__half2 h) {
    return *reinterpret_cast<uint32_t*>(&h);
}

__device__ __forceinline__ void cp16(uint32_t dst, const void* src, bool valid) {
    int sz = valid ? 16 : 0;   // sz=0 zero-fills, reads nothing
    asm volatile("cp.async.cg.shared.global [%0], [%1], 16, %2;\n"
                 :: "r"(dst), "l"(src), "r"(sz));
}

__device__ __forceinline__ void ldsm_x4(uint32_t* r, uint32_t addr) {
    asm volatile("ldmatrix.sync.aligned.m8n8.x4.shared.b16 {%0,%1,%2,%3}, [%4];"
                 : "=r"(r[0]), "=r"(r[1]), "=r"(r[2]), "=r"(r[3]) : "r"(addr));
}
__device__ __forceinline__ void ldsm_x4_t(uint32_t* r, uint32_t addr) {
    asm volatile("ldmatrix.sync.aligned.m8n8.x4.trans.shared.b16 {%0,%1,%2,%3}, [%4];"
                 : "=r"(r[0]), "=r"(r[1]), "=r"(r[2]), "=r"(r[3]) : "r"(addr));
}

__device__ __forceinline__ void mma_f16(float* c, const uint32_t* a,
                                        uint32_t b0, uint32_t b1) {
    asm volatile(
        "mma.sync.aligned.m16n8k16.row.col.f32.f16.f16.f32 "
        "{%0,%1,%2,%3},{%4,%5,%6,%7},{%8,%9},{%0,%1,%2,%3};"
        : "+f"(c[0]), "+f"(c[1]), "+f"(c[2]), "+f"(c[3])
        : "r"(a[0]), "r"(a[1]), "r"(a[2]), "r"(a[3]), "r"(b0), "r"(b1));
}

// ---- tile scan helper ----
__device__ __forceinline__ int tile_scan(const int* msz, int mt, int* e_out,
                                         int* row_out, int* mlen_out) {
    int acc_rows = 0, acc_tiles = 0;
    for (int e = 0; e < NEXP; e++) {
        int m  = msz[e];
        int nt = (m + BM - 1) >> 7;
        if (mt < acc_tiles + nt) {
            int lt    = mt - acc_tiles;
            *e_out    = e;
            *row_out  = acc_rows + lt * BM;
            *mlen_out = min(BM, m - lt * BM);
            return 1;
        }
        acc_tiles += nt;
        acc_rows  += m;
    }
    return 0;
}

// ---- merged prepass: blocks [0,320) = x-cvt + lora-A (256 thr, 8 warps);
//      blocks >=320 = streaming w cvt ----
#define LSA 80   /* x smem stride (bytes) */
#define LSW 48   /* w_a smem stride */
__global__ void __launch_bounds__(PTHREADS)
prepass_kernel(const float* __restrict__ x,
               const int*   __restrict__ m_sizes,
               const float* __restrict__ w_a,
               const float4* __restrict__ wb_src,   /* w_base fp32 */
               const float4* __restrict__ ws_src)   /* w_b fp32 */
{
    __shared__ __align__(128) char smem[2 * 128 * LSA + 2 * 32 * LSW + 256];
    const int tid = threadIdx.x;

    if (blockIdx.x >= MAX_MTILES) {
        // ---- streaming fp32->fp16 convert of w_base then w_b ----
        const int nwb = (int)((size_t)NEXP * IN_DIM * OUT_DIM / 4);
        const int nws = (int)((size_t)NEXP * RRANK * OUT_DIM / 4);
        const int ntot = nwb + nws;
        uint2* wb_dst = (uint2*)g_wbh;
        uint2* ws_dst = (uint2*)g_wsh;
        const int stride = CVT_BLOCKS * PTHREADS;
        for (int i = (blockIdx.x - MAX_MTILES) * PTHREADS + tid; i < ntot; i += stride) {
            float4 f;
            if (i < nwb) f = wb_src[i];
            else         f = ws_src[i - nwb];
            uint2 u;
            u.x = h2u(__floats2half2_rn(f.x, f.y));
            u.y = h2u(__floats2half2_rn(f.z, f.w));
            if (i < nwb) wb_dst[i] = u;
            else         ws_dst[i - nwb] = u;
        }
        return;
    }

    // ---- lora-A path (block = one m-tile, 8 warps, warp tile 16x16) ----
    char* Xs  = smem;
    char* Was = smem + 2 * 128 * LSA;
    int*  msz = (int*)(smem + 2 * 128 * LSA + 2 * 32 * LSW);
    const uint32_t sbx = (uint32_t)__cvta_generic_to_shared(Xs);
    const uint32_t sbw = (uint32_t)__cvta_generic_to_shared(Was);

    const int lane = tid & 31;
    const int warp = tid >> 5;   // 0..7, rows [16w, 16w+16)

    if (tid < NEXP) msz[tid] = m_sizes[tid];
    __syncthreads();

    int e, row_start, m_len;
    if (!tile_scan(msz, blockIdx.x, &e, &row_start, &m_len)) return;

    const float* xg = x   + (size_t)row_start * IN_DIM;
    const float* ag = w_a + (size_t)e * IN_DIM * RRANK;
    __half*      xo = g_xh + (size_t)row_start * IN_DIM;

    float acc[2][4];   // 2 n-frags (R=16) x 4
    #pragma unroll
    for (int j = 0; j < 2; j++)
        #pragma unroll
        for (int q = 0; q < 4; q++) acc[j][q] = 0.f;

    float4 fx[4], fw;

    auto load_regs = [&](int kt) {
        const int k0 = kt * BK;
        #pragma unroll
        for (int j = 0; j < 4; j++) {
            int idx = tid + j * PTHREADS;          // 0..1023
            int row = idx >> 3, c = idx & 7;
            bool v = (row_start + row) < T_TOK;
            fx[j] = v ? *(const float4*)(xg + (size_t)row * IN_DIM + k0 + c * 4)
                      : make_float4(0.f, 0.f, 0.f, 0.f);
        }
        if (tid < 128) {
            int k = tid >> 2, rq = tid & 3;        // 32 k x 4 float4
            fw = *(const float4*)(ag + (size_t)(k0 + k) * RRANK + rq * 4);
        }
    };

    auto store_stage = [&](int kt) {
        const int st = kt & 1;
        char* X = Xs  + st * 128 * LSA;
        char* W = Was + st * 32 * LSW;
        const int k0 = kt * BK;
        #pragma unroll
        for (int j = 0; j < 4; j++) {
            int idx = tid + j * PTHREADS;
            int row = idx >> 3, c = idx & 7;
            uint2 u;
            u.x = h2u(__floats2half2_rn(fx[j].x, fx[j].y));
            u.y = h2u(__floats2half2_rn(fx[j].z, fx[j].w));
            *(uint2*)(X + row * LSA + c * 8) = u;
            if ((row_start + row) < T_TOK)
                *(uint2*)(xo + (size_t)row * IN_DIM + k0 + c * 4) = u;
        }
        if (tid < 128) {
            int k = tid >> 2, rq = tid & 3;
            uint2 u;
            u.x = h2u(__floats2half2_rn(fw.x, fw.y));
            u.y = h2u(__floats2half2_rn(fw.z, fw.w));
            *(uint2*)(W + k * LSW + rq * 8) = u;
        }
    };

    const uint32_t a_off = (uint32_t)((warp * 16 + (lane & 15)) * LSA + (lane >> 4) * 16);
    const uint32_t w_off = (uint32_t)((lane & 15) * LSW + (lane >> 4) * 16);

    auto compute = [&](int kt) {
        const int st = kt & 1;
        const uint32_t Xb = sbx + st * 128 * LSA + a_off;
        const uint32_t Wb = sbw + st * 32 * LSW + w_off;
        #pragma unroll
        for (int ks = 0; ks < 2; ks++) {
            uint32_t am[4];
            ldsm_x4(am, Xb + ks * 32);
            uint32_t bf[4];
            ldsm_x4_t(bf, Wb + ks * 16 * LSW);
            mma_f16(acc[0], am, bf[0], bf[1]);
            mma_f16(acc[1], am, bf[2], bf[3]);
        }
    };

    load_regs(0);
    store_stage(0);
    __syncthreads();
    #pragma unroll 1
    for (int kt = 0; kt < KT3; kt++) {
        if (kt + 1 < KT3) load_regs(kt + 1);
        compute(kt);
        if (kt + 1 < KT3) {
            store_stage(kt + 1);
            __syncthreads();
        }
    }

    // store a * SCALING (only rows of THIS expert)
    {
        const int r0 = warp * 16 + (lane >> 2);
        const int c0 = 2 * (lane & 3);
        #pragma unroll
        for (int nf = 0; nf < 2; nf++) {
            int c = nf * 8 + c0;
            if (r0 < m_len)
                *(__half2*)(g_ah + (size_t)(row_start + r0) * RRANK + c) =
                    __floats2half2_rn(acc[nf][0] * SCALING, acc[nf][1] * SCALING);
            if (r0 + 8 < m_len)
                *(__half2*)(g_ah + (size_t)(row_start + r0 + 8) * RRANK + c) =
                    __floats2half2_rn(acc[nf][2] * SCALING, acc[nf][3] * SCALING);
        }
    }
}

// ---- main GEMM (EXACT round-11 structure): y = x@w_base[e] + a2@w_b[e] ----
__global__ __launch_bounds__(NTHREADS, 2)
void lora_moe_h7(const int* __restrict__ m_sizes, float* __restrict__ out) {
    extern __shared__ __align__(128) char smem[];
    const uint32_t sb = (uint32_t)__cvta_generic_to_shared(smem);

    const int tid  = threadIdx.x;
    const int lane = tid & 31;
    const int warp = tid >> 5;
    const int wm   = warp & 1;   // m half (64 rows)
    const int wn   = warp >> 1;  // n half (64 cols)

    int* msz = (int*)(smem + SM_MSZ);
    if (tid < NEXP) msz[tid] = m_sizes[tid];
    __syncthreads();

    int e, row_start, m_len;
    if (!tile_scan(msz, blockIdx.y, &e, &row_start, &m_len)) return;

    const int n0 = blockIdx.x * BN;
    const __half* xg  = g_xh  + (size_t)row_start * IN_DIM;
    const __half* bg  = g_wbh + (size_t)e * IN_DIM * OUT_DIM + n0;
    const __half* wbg = g_wsh + (size_t)e * RRANK  * OUT_DIM + n0;

    float acc[4][8][4];
    #pragma unroll
    for (int i = 0; i < 4; i++)
        #pragma unroll
        for (int j = 0; j < 8; j++)
            #pragma unroll
            for (int q = 0; q < 4; q++) acc[i][j][q] = 0.f;

    auto load_stage = [&](int kt) {
        const int st = kt & 3;
        const uint32_t A = sb + SM_A + st * A_STG;
        const uint32_t B = sb + SM_B + st * B_STG;
        const int k0 = kt * BK;
        #pragma unroll
        for (int j = 0; j < 4; j++) {
            int idx = tid + j * NTHREADS;
            int row = idx >> 2, kc = idx & 3;
            bool v = (row_start + row) < T_TOK;
            cp16(A + row * SA + kc * 16, xg + (size_t)row * IN_DIM + k0 + kc * 8, v);
        }
        #pragma unroll
        for (int j = 0; j < 4; j++) {
            int idx = tid + j * NTHREADS;
            int k = idx >> 4, nq = idx & 15;
            cp16(B + k * SB + nq * 16, bg + (size_t)(k0 + k) * OUT_DIM + nq * 8, true);
        }
        asm volatile("cp.async.commit_group;\n");
    };

    const uint32_t a_off = (uint32_t)((wm * 64 + (lane & 15)) * SA + (lane >> 4) * 16);
    const uint32_t b_off = (uint32_t)((lane & 15) * SB + (wn * 64 + (lane >> 4) * 8) * 2);

    auto compute = [&](int kt) {
        const int st = kt & 3;
        const uint32_t Ab = sb + SM_A + st * A_STG + a_off;
        const uint32_t Bb = sb + SM_B + st * B_STG + b_off;
        #pragma unroll
        for (int ks = 0; ks < 2; ks++) {
            uint32_t am[4][4];
            #pragma unroll
            for (int mf = 0; mf < 4; mf++)
                ldsm_x4(am[mf], Ab + mf * 16 * SA + ks * 32);
            #pragma unroll
            for (int p = 0; p < 4; p++) {
                uint32_t bf[4];
                ldsm_x4_t(bf, Bb + ks * 16 * SB + p * 32);
                #pragma unroll
                for (int mf = 0; mf < 4; mf++) {
                    mma_f16(acc[mf][2 * p],     am[mf], bf[0], bf[1]);
                    mma_f16(acc[mf][2 * p + 1], am[mf], bf[2], bf[3]);
                }
            }
        }
    };

    // ---- 4-stage pipeline, depth-3 flight, one barrier per stage ----
    load_stage(0);
    load_stage(1);
    load_stage(2);
    #pragma unroll 1
    for (int kt = 0; kt < KT3; kt++) {
        if (kt < KT3 - 2)       asm volatile("cp.async.wait_group 2;\n");
        else if (kt == KT3 - 2) asm volatile("cp.async.wait_group 1;\n");
        else                    asm volatile("cp.async.wait_group 0;\n");
        __syncthreads();
        if (kt + 3 < KT3) load_stage(kt + 3);
        compute(kt);
    }
    __syncthreads();

    // ---- LoRA epilogue: load a2 (g_ah) + w_b, one K=16 mma pass ----
    {
        const uint32_t Asc = sb + SM_A;
        #pragma unroll
        for (int j = 0; j < 2; j++) {
            int idx = tid + j * NTHREADS;
            int row = idx >> 1, c = idx & 1;
            bool v = (row_start + row) < T_TOK;
            cp16(Asc + row * SAC + c * 16,
                 g_ah + (size_t)(row_start + row) * RRANK + c * 8, v);
        }
        asm volatile("cp.async.commit_group;\n");
        char* Wbs = smem + SM_B;
        #pragma unroll
        for (int j = 0; j < 2; j++) {
            int idx = tid + j * NTHREADS;
            int k = idx >> 4, nq = idx & 15;
            uint4 v = *(const uint4*)(wbg + (size_t)k * OUT_DIM + nq * 8);
            *(uint4*)(Wbs + k * SB + nq * 16) = v;
        }
        asm volatile("cp.async.wait_group 0;\n");
    }
    __syncthreads();

    {
        const int row = wm * 64 + (lane >> 2);
        uint32_t am[4][4];
        #pragma unroll
        for (int mf = 0; mf < 4; mf++) {
            const uint32_t base = sb + SM_A + (row + mf * 16) * SAC + (lane & 3) * 4;
            asm volatile("ld.shared.b32 %0, [%1];" : "=r"(am[mf][0]) : "r"(base));
            asm volatile("ld.shared.b32 %0, [%1];" : "=r"(am[mf][1]) : "r"(base + 8 * SAC));
            asm volatile("ld.shared.b32 %0, [%1];" : "=r"(am[mf][2]) : "r"(base + 16));
            asm volatile("ld.shared.b32 %0, [%1];" : "=r"(am[mf][3]) : "r"(base + 8 * SAC + 16));
        }
        const uint32_t Bb = sb + SM_B + b_off;
        #pragma unroll
        for (int p = 0; p < 4; p++) {
            uint32_t bf[4];
            ldsm_x4_t(bf, Bb + p * 32);
            #pragma unroll
            for (int mf = 0; mf < 4; mf++) {
                mma_f16(acc[mf][2 * p],     am[mf], bf[0], bf[1]);
                mma_f16(acc[mf][2 * p + 1], am[mf], bf[2], bf[3]);
            }
        }
    }

    // ---- store ----
    {
        float* og = out + (size_t)row_start * OUT_DIM + n0;
        const int r0s = wm * 64 + (lane >> 2);
        const int c0s = wn * 64 + 2 * (lane & 3);
        #pragma unroll
        for (int mf = 0; mf < 4; mf++) {
            const int r1 = r0s + mf * 16;
            #pragma unroll
            for (int nf = 0; nf < 8; nf++) {
                const int cc = c0s + nf * 8;
                if (r1 < m_len)
                    *reinterpret_cast<float2*>(og + (size_t)r1 * OUT_DIM + cc) =
                        make_float2(acc[mf][nf][0], acc[mf][nf][1]);
                if (r1 + 8 < m_len)
                    *reinterpret_cast<float2*>(og + (size_t)(r1 + 8) * OUT_DIM + cc) =
                        make_float2(acc[mf][nf][2], acc[mf][nf][3]);
            }
        }
    }
}

extern "C" void kernel_launch(void* const* d_in, const int* in_sizes, int n_in,
                              void* d_out, int out_size) {
    const float* x      = (const float*)d_in[0];
    const int*   msz    = (const int*)  d_in[1];
    const float* w_base = (const float*)d_in[2];
    const float* w_a    = (const float*)d_in[3];
    const float* w_b    = (const float*)d_in[4];
    float*       out    = (float*)d_out;

    prepass_kernel<<<PRE_GRID, PTHREADS>>>(x, msz, w_a,
                                           (const float4*)w_base, (const float4*)w_b);

    static int cfg_done = 0;
    if (!cfg_done) {
        cudaFuncSetAttribute(lora_moe_h7,
                             cudaFuncAttributeMaxDynamicSharedMemorySize, SMEM_BYTES);
        cfg_done = 1;
    }
    dim3 grid(NT, MAX_MTILES);
    lora_moe_h7<<<grid, NTHREADS, SMEM_BYTES>>>(msz, out);
}